// round 11
// baseline (speedup 1.0000x reference)
#include <cuda_runtime.h>
#include <cuda_bf16.h>
#include <stdint.h>

#define N_NODES 50000
#define N_EDGES 800000
#define N_GRAPHS 256
#define DIN0 32
#define HID 96
#define BN_EPS 1e-5f

// ---------------- device scratch (static, allowed) ----------------
__device__ float g_h[(size_t)N_NODES * HID];
__device__ float g_agg[(size_t)N_NODES * HID];
__device__ float g_z[(size_t)N_NODES * HID];
__device__ float g_pool[N_GRAPHS * HID];

// vectorized fire-and-forget global reduction (sm_90+)
__device__ __forceinline__ void red_add_v4(float* addr, float4 v) {
    asm volatile("red.global.add.v4.f32 [%0], {%1, %2, %3, %4};"
                 :: "l"(addr), "f"(v.x), "f"(v.y), "f"(v.z), "f"(v.w)
                 : "memory");
}

__device__ __forceinline__ float to_tf32(float x) {
    uint32_t u;
    asm("cvt.rna.tf32.f32 %0, %1;" : "=r"(u) : "f"(x));
    return __uint_as_float(u);
}

__device__ __forceinline__ void mma_tf32(float* c, uint32_t a0, uint32_t a1,
                                         uint32_t a2, uint32_t a3,
                                         uint32_t b0, uint32_t b1) {
    asm volatile(
        "mma.sync.aligned.m16n8k8.row.col.f32.tf32.tf32.f32 "
        "{%0,%1,%2,%3}, {%4,%5,%6,%7}, {%8,%9}, {%0,%1,%2,%3};"
        : "+f"(c[0]), "+f"(c[1]), "+f"(c[2]), "+f"(c[3])
        : "r"(a0), "r"(a1), "r"(a2), "r"(a3), "r"(b0), "r"(b1));
}

// ---------------- small kernels ----------------
__global__ void copy_x_kernel(const float* __restrict__ x) {
    int i = blockIdx.x * blockDim.x + threadIdx.x;
    int total = N_NODES * DIN0 / 4;
    if (i < total) ((float4*)g_agg)[i] = ((const float4*)x)[i];
}

// edge scatter: agg[dst] += h[src], one red.v4 per (edge, lane)
template<int DIN>
__global__ void edge_kernel(const float* __restrict__ h,
                            const int* __restrict__ ei,
                            float* __restrict__ agg) {
    const int VPR = DIN / 4;
    int t = blockIdx.x * blockDim.x + threadIdx.x;
    int e = t / VPR;
    int lane = t - e * VPR;
    if (e >= N_EDGES) return;
    int s = __ldg(&ei[e]);
    int d = __ldg(&ei[N_EDGES + e]);
    float4 v = *(const float4*)(h + (size_t)s * DIN + lane * 4);
    red_add_v4(agg + (size_t)d * DIN + lane * 4, v);
}

// ---------------- TF32 tensor-core GEMM: out = epi(A[N x DIN] @ W[DIN x 96]) --
// 256 threads = 8 warps. Block tile M=128 x N=96.
// Warp (mw, nw): 32-row slab (2 m16 frags) x 48-col slab (6 n8 frags).
// W fragment-packed in smem (Bp): 1 LDS.64 per B frag.
// A k-chunks of 8, transposed As[k][row] (stride 136), 2 smem bufs,
// register prefetch depth 2 (chunks kt+1, kt+2 in regs; LDG kt+3 at loop top).
template<int DIN, bool HAS_BN, bool DUAL>
__global__ void __launch_bounds__(256, 3) gemm_kernel(
    const float* __restrict__ A, const float* __restrict__ W,
    const float* __restrict__ bias,
    const float* __restrict__ gamma, const float* __restrict__ beta,
    const float* __restrict__ rmean, const float* __restrict__ rvar,
    float* __restrict__ out, float* __restrict__ out2)
{
    constexpr int H = 96;
    constexpr int NKC = DIN / 8;
    __shared__ float Bp[DIN * 96];          // fragment-packed W (36.9KB @ DIN=96)
    __shared__ float As[2][8][136];         // A^T chunk (8.7KB)

    const int tid  = threadIdx.x;
    const int warp = tid >> 5;
    const int lane = tid & 31;
    const int g    = lane >> 2;             // 0..7
    const int tg   = lane & 3;              // 0..3
    const int mw   = warp & 3;              // 0..3 -> 32-row slab
    const int nw   = warp >> 2;             // 0..1 -> 48-col slab
    const int row0 = blockIdx.x * 128;

    // pack W into MMA-fragment layout:
    // frag = (kt*2 + nw)*6 + ni ; within frag: [lane][hi] (hi: k low/high half)
    for (int i = tid; i < DIN * 96; i += 256) {
        int k = i / 96, n = i - k * 96;
        int kt = k >> 3, rem = k & 7;
        int frag = ((kt * 2 + (n / 48)) * 6) + ((n % 48) >> 3);
        int ln = (n & 7) * 4 + (rem & 3);
        Bp[frag * 64 + ln * 2 + (rem >> 2)] = to_tf32(W[i]);
    }

    const int r  = tid & 127;
    const int kv = tid >> 7;                // 0..1 -> k sub-offset 4*kv

    float acc[2][6][4];
    #pragma unroll
    for (int mi = 0; mi < 2; mi++)
        #pragma unroll
        for (int ni = 0; ni < 6; ni++)
            #pragma unroll
            for (int q = 0; q < 4; q++) acc[mi][ni][q] = 0.f;

    const int gr = row0 + r;
    const bool rok = (gr < N_NODES);
    const float* arow = A + (size_t)gr * DIN + kv * 4;

    // stage chunk 0 directly
    {
        float4 v = rok ? *(const float4*)(arow)
                       : make_float4(0.f, 0.f, 0.f, 0.f);
        As[0][kv * 4 + 0][r] = to_tf32(v.x);
        As[0][kv * 4 + 1][r] = to_tf32(v.y);
        As[0][kv * 4 + 2][r] = to_tf32(v.z);
        As[0][kv * 4 + 3][r] = to_tf32(v.w);
    }
    // register prefetch: chunks 1 and 2
    float4 pre0 = (NKC > 1 && rok) ? *(const float4*)(arow + 8)
                                   : make_float4(0.f, 0.f, 0.f, 0.f);
    float4 pre1 = (NKC > 2 && rok) ? *(const float4*)(arow + 16)
                                   : make_float4(0.f, 0.f, 0.f, 0.f);
    __syncthreads();

    int buf = 0;
    for (int kt = 0; kt < NKC; kt++) {
        // early: store chunk kt+1 into the free buffer, shift, issue LDG kt+3
        if (kt + 1 < NKC) {
            As[buf ^ 1][kv * 4 + 0][r] = to_tf32(pre0.x);
            As[buf ^ 1][kv * 4 + 1][r] = to_tf32(pre0.y);
            As[buf ^ 1][kv * 4 + 2][r] = to_tf32(pre0.z);
            As[buf ^ 1][kv * 4 + 3][r] = to_tf32(pre0.w);
            pre0 = pre1;
            pre1 = (kt + 3 < NKC && rok) ? *(const float4*)(arow + (kt + 3) * 8)
                                         : make_float4(0.f, 0.f, 0.f, 0.f);
        }

        // B fragments: one LDS.64 each, conflict-free
        uint32_t bf[6][2];
        #pragma unroll
        for (int ni = 0; ni < 6; ni++) {
            float2 b = *(const float2*)&Bp[(((kt * 2 + nw) * 6) + ni) * 64 + lane * 2];
            bf[ni][0] = __float_as_uint(b.x);
            bf[ni][1] = __float_as_uint(b.y);
        }
        #pragma unroll
        for (int mi = 0; mi < 2; mi++) {
            int ra = mw * 32 + mi * 16 + g;
            uint32_t a0 = __float_as_uint(As[buf][tg][ra]);
            uint32_t a1 = __float_as_uint(As[buf][tg][ra + 8]);
            uint32_t a2 = __float_as_uint(As[buf][tg + 4][ra]);
            uint32_t a3 = __float_as_uint(As[buf][tg + 4][ra + 8]);
            #pragma unroll
            for (int ni = 0; ni < 6; ni++)
                mma_tf32(acc[mi][ni], a0, a1, a2, a3, bf[ni][0], bf[ni][1]);
        }

        if (kt + 1 < NKC) __syncthreads();
        buf ^= 1;
    }

    // epilogue: per-thread cols = nw*48 + ni*8 + 2*tg (+1)
    float sc[6][2], sh[6][2];
    #pragma unroll
    for (int ni = 0; ni < 6; ni++)
        #pragma unroll
        for (int jj = 0; jj < 2; jj++) {
            int c = nw * 48 + ni * 8 + 2 * tg + jj;
            if (HAS_BN) {
                float s = gamma[c] * rsqrtf(rvar[c] + BN_EPS);
                sc[ni][jj] = s;
                sh[ni][jj] = (bias[c] - rmean[c]) * s + beta[c];
            } else {
                sc[ni][jj] = 1.f;
                sh[ni][jj] = bias[c];
            }
        }

    #pragma unroll
    for (int mi = 0; mi < 2; mi++) {
        int ra = row0 + mw * 32 + mi * 16 + g;
        int rb = ra + 8;
        #pragma unroll
        for (int ni = 0; ni < 6; ni++) {
            int col = nw * 48 + ni * 8 + 2 * tg;
            if (ra < N_NODES) {
                float2 o;
                o.x = fmaxf(fmaf(acc[mi][ni][0], sc[ni][0], sh[ni][0]), 0.f);
                o.y = fmaxf(fmaf(acc[mi][ni][1], sc[ni][1], sh[ni][1]), 0.f);
                *(float2*)(out + (size_t)ra * H + col) = o;
                if (DUAL) *(float2*)(out2 + (size_t)ra * H + col) = o;
            }
            if (rb < N_NODES) {
                float2 o;
                o.x = fmaxf(fmaf(acc[mi][ni][2], sc[ni][0], sh[ni][0]), 0.f);
                o.y = fmaxf(fmaf(acc[mi][ni][3], sc[ni][1], sh[ni][1]), 0.f);
                *(float2*)(out + (size_t)rb * H + col) = o;
                if (DUAL) *(float2*)(out2 + (size_t)rb * H + col) = o;
            }
        }
    }
}

// ---------------- pooling (batch sorted -> segment sums, no atomics) ----------
__global__ void __launch_bounds__(96) pool_kernel(const int* __restrict__ batch,
                                                  float* __restrict__ pool) {
    int b = blockIdx.x;
    int c = threadIdx.x;
    int lo = 0, hi = N_NODES;
    while (lo < hi) { int m = (lo + hi) >> 1; if (batch[m] < b) lo = m + 1; else hi = m; }
    int start = lo;
    hi = N_NODES;
    while (lo < hi) { int m = (lo + hi) >> 1; if (batch[m] < b + 1) lo = m + 1; else hi = m; }
    int end = lo;

    float acc = 0.f;
    for (int n = start; n < end; n++)
        acc += g_h[(size_t)n * HID + c];
    pool[b * HID + c] = acc;
}

__global__ void head_kernel(const int* __restrict__ r_target,
                            const float* __restrict__ head_w,
                            const float* __restrict__ head_b,
                            const float* __restrict__ pool,
                            float* __restrict__ out) {
    int b = threadIdx.x;
    if (b >= N_GRAPHS) return;
    int t = r_target[b];
    const float4* w = (const float4*)(head_w + (size_t)t * HID);
    const float4* p = (const float4*)(pool + (size_t)b * HID);
    float acc = 0.f;
    #pragma unroll
    for (int k = 0; k < HID / 4; k++) {
        float4 wv = w[k], pv = p[k];
        acc = fmaf(pv.x, wv.x, acc);
        acc = fmaf(pv.y, wv.y, acc);
        acc = fmaf(pv.z, wv.z, acc);
        acc = fmaf(pv.w, wv.w, acc);
    }
    out[b] = acc + head_b[t];
}

// ---------------- launch ----------------
extern "C" void kernel_launch(void* const* d_in, const int* in_sizes, int n_in,
                              void* d_out, int out_size) {
    const float* x    = (const float*)d_in[0];
    const int*   ei   = (const int*)d_in[1];
    const int*   bat  = (const int*)d_in[2];
    const int*   rtg  = (const int*)d_in[3];

    const float* w_in[3]  = {(const float*)d_in[4],  (const float*)d_in[12], (const float*)d_in[20]};
    const float* b_in[3]  = {(const float*)d_in[5],  (const float*)d_in[13], (const float*)d_in[21]};
    const float* gam[3]   = {(const float*)d_in[6],  (const float*)d_in[14], (const float*)d_in[22]};
    const float* bet[3]   = {(const float*)d_in[7],  (const float*)d_in[15], (const float*)d_in[23]};
    const float* rme[3]   = {(const float*)d_in[8],  (const float*)d_in[16], (const float*)d_in[24]};
    const float* rva[3]   = {(const float*)d_in[9],  (const float*)d_in[17], (const float*)d_in[25]};
    const float* w_out[3] = {(const float*)d_in[10], (const float*)d_in[18], (const float*)d_in[26]};
    const float* b_out[3] = {(const float*)d_in[11], (const float*)d_in[19], (const float*)d_in[27]};
    const float* head_w   = (const float*)d_in[28];
    const float* head_b   = (const float*)d_in[29];
    float* out = (float*)d_out;

    float *hbuf, *aggbuf, *zbuf, *poolbuf;
    cudaGetSymbolAddress((void**)&hbuf, g_h);
    cudaGetSymbolAddress((void**)&aggbuf, g_agg);
    cudaGetSymbolAddress((void**)&zbuf, g_z);
    cudaGetSymbolAddress((void**)&poolbuf, g_pool);

    const int TB = 256;
    const int GB = 256;
    const int gemm_blocks = (N_NODES + 127) / 128;

    // ---- layer 1 (Din=32) ----
    copy_x_kernel<<<(N_NODES * DIN0 / 4 + TB - 1) / TB, TB>>>(x);
    {
        int tot = N_EDGES * (DIN0 / 4);
        edge_kernel<DIN0><<<(tot + TB - 1) / TB, TB>>>(x, ei, aggbuf);
    }
    gemm_kernel<DIN0, true, false><<<gemm_blocks, GB>>>(
        aggbuf, w_in[0], b_in[0], gam[0], bet[0], rme[0], rva[0], zbuf, nullptr);
    gemm_kernel<HID, false, true><<<gemm_blocks, GB>>>(
        zbuf, w_out[0], b_out[0], nullptr, nullptr, nullptr, nullptr, hbuf, aggbuf);

    // ---- layer 2 ----
    {
        int tot = N_EDGES * (HID / 4);
        edge_kernel<HID><<<(tot + TB - 1) / TB, TB>>>(hbuf, ei, aggbuf);
    }
    gemm_kernel<HID, true, false><<<gemm_blocks, GB>>>(
        aggbuf, w_in[1], b_in[1], gam[1], bet[1], rme[1], rva[1], zbuf, nullptr);
    gemm_kernel<HID, false, true><<<gemm_blocks, GB>>>(
        zbuf, w_out[1], b_out[1], nullptr, nullptr, nullptr, nullptr, hbuf, aggbuf);

    // ---- layer 3 ----
    {
        int tot = N_EDGES * (HID / 4);
        edge_kernel<HID><<<(tot + TB - 1) / TB, TB>>>(hbuf, ei, aggbuf);
    }
    gemm_kernel<HID, true, false><<<gemm_blocks, GB>>>(
        aggbuf, w_in[2], b_in[2], gam[2], bet[2], rme[2], rva[2], zbuf, nullptr);
    gemm_kernel<HID, false, false><<<gemm_blocks, GB>>>(
        zbuf, w_out[2], b_out[2], nullptr, nullptr, nullptr, nullptr, hbuf, nullptr);

    // ---- pooling + head ----
    pool_kernel<<<N_GRAPHS, 96>>>(bat, poolbuf);
    head_kernel<<<1, 256>>>(rtg, head_w, head_b, poolbuf, out);
}

// round 12
// speedup vs baseline: 1.0407x; 1.0407x over previous
#include <cuda_runtime.h>
#include <cuda_bf16.h>
#include <stdint.h>

#define N_NODES 50000
#define N_EDGES 800000
#define N_GRAPHS 256
#define DIN0 32
#define HID 96
#define BN_EPS 1e-5f

// ---------------- device scratch (static, allowed) ----------------
__device__ float g_h[(size_t)N_NODES * HID];
__device__ float g_agg[(size_t)N_NODES * HID];
__device__ float g_z[(size_t)N_NODES * HID];
__device__ float g_pool[N_GRAPHS * HID];

// vectorized fire-and-forget global reduction (sm_90+)
__device__ __forceinline__ void red_add_v4(float* addr, float4 v) {
    asm volatile("red.global.add.v4.f32 [%0], {%1, %2, %3, %4};"
                 :: "l"(addr), "f"(v.x), "f"(v.y), "f"(v.z), "f"(v.w)
                 : "memory");
}

__device__ __forceinline__ float to_tf32(float x) {
    uint32_t u;
    asm("cvt.rna.tf32.f32 %0, %1;" : "=r"(u) : "f"(x));
    return __uint_as_float(u);
}

__device__ __forceinline__ void mma_tf32(float* c, uint32_t a0, uint32_t a1,
                                         uint32_t a2, uint32_t a3,
                                         uint32_t b0, uint32_t b1) {
    asm volatile(
        "mma.sync.aligned.m16n8k8.row.col.f32.tf32.tf32.f32 "
        "{%0,%1,%2,%3}, {%4,%5,%6,%7}, {%8,%9}, {%0,%1,%2,%3};"
        : "+f"(c[0]), "+f"(c[1]), "+f"(c[2]), "+f"(c[3])
        : "r"(a0), "r"(a1), "r"(a2), "r"(a3), "r"(b0), "r"(b1));
}

// ---------------- small kernels ----------------
__global__ void copy_x_kernel(const float* __restrict__ x) {
    int i = blockIdx.x * blockDim.x + threadIdx.x;
    int total = N_NODES * DIN0 / 4;
    if (i < total) ((float4*)g_agg)[i] = ((const float4*)x)[i];
}

// edge scatter: agg[dst] += h[src], one red.v4 per (edge, lane)
template<int DIN>
__global__ void edge_kernel(const float* __restrict__ h,
                            const int* __restrict__ ei,
                            float* __restrict__ agg) {
    const int VPR = DIN / 4;
    int t = blockIdx.x * blockDim.x + threadIdx.x;
    int e = t / VPR;
    int lane = t - e * VPR;
    if (e >= N_EDGES) return;
    int s = __ldg(&ei[e]);
    int d = __ldg(&ei[N_EDGES + e]);
    float4 v = *(const float4*)(h + (size_t)s * DIN + lane * 4);
    red_add_v4(agg + (size_t)d * DIN + lane * 4, v);
}

// ---------------- TF32 tensor-core GEMM: out = epi(A[N x DIN] @ W[DIN x 96]) --
// 256 threads = 8 warps. Block tile M=128 x N=96.
// Warp (mw, nw): 32-row slab (2 m16 frags) x 48-col slab (6 n8 frags).
// W transposed+padded in smem (one-time load, one sync). A fragments loaded
// DIRECTLY from global via predicated LDG.32 + cvt.rna — no A smem, no
// mainloop __syncthreads. Warps run independently; LDGs batched across chunks.
template<int DIN, bool HAS_BN, bool DUAL>
__global__ void __launch_bounds__(256, 3) gemm_kernel(
    const float* __restrict__ A, const float* __restrict__ W,
    const float* __restrict__ bias,
    const float* __restrict__ gamma, const float* __restrict__ beta,
    const float* __restrict__ rmean, const float* __restrict__ rvar,
    float* __restrict__ out, float* __restrict__ out2)
{
    constexpr int H = 96;
    constexpr int NKC = DIN / 8;
    constexpr int WSTR = DIN + 4;
    __shared__ float Wt[H * WSTR];          // W^T: Wt[n][k] (38.4KB @ DIN=96)

    const int tid  = threadIdx.x;
    const int warp = tid >> 5;
    const int lane = tid & 31;
    const int g    = lane >> 2;             // 0..7
    const int tg   = lane & 3;              // 0..3
    const int mw   = warp & 3;              // 0..3 -> 32-row slab
    const int nw   = warp >> 2;             // 0..1 -> 48-col slab
    const int row0 = blockIdx.x * 128;

    // load W transposed + tf32-rounded (only block-wide cooperation)
    for (int i = tid; i < DIN * H; i += 256) {
        int k = i / H, n = i - k * H;
        Wt[n * WSTR + k] = to_tf32(W[i]);
    }
    __syncthreads();

    // per-thread A row bases (4 rows: mi*16 + {0,8})
    const int rl = row0 + mw * 32 + g;
    const bool ok0 = (rl      < N_NODES);
    const bool ok1 = (rl + 8  < N_NODES);
    const bool ok2 = (rl + 16 < N_NODES);
    const bool ok3 = (rl + 24 < N_NODES);
    const float* ap = A + (size_t)rl * DIN + tg;

    float acc[2][6][4];
    #pragma unroll
    for (int mi = 0; mi < 2; mi++)
        #pragma unroll
        for (int ni = 0; ni < 6; ni++)
            #pragma unroll
            for (int q = 0; q < 4; q++) acc[mi][ni][q] = 0.f;

    #pragma unroll 2
    for (int kt = 0; kt < NKC; kt++) {
        const int kb = kt * 8;

        // A fragments: predicated global loads (L1/L2-hot), then tf32 round
        float a00 = ok0 ? ap[kb]                : 0.f;   // (rl,    kb+tg)
        float a02 = ok0 ? ap[kb + 4]            : 0.f;   // (rl,    kb+tg+4)
        float a01 = ok1 ? ap[8  * DIN + kb]     : 0.f;   // (rl+8,  kb+tg)
        float a03 = ok1 ? ap[8  * DIN + kb + 4] : 0.f;
        float a10 = ok2 ? ap[16 * DIN + kb]     : 0.f;   // (rl+16, kb+tg)
        float a12 = ok2 ? ap[16 * DIN + kb + 4] : 0.f;
        float a11 = ok3 ? ap[24 * DIN + kb]     : 0.f;   // (rl+24, kb+tg)
        float a13 = ok3 ? ap[24 * DIN + kb + 4] : 0.f;

        uint32_t A0[2][4];
        A0[0][0] = __float_as_uint(to_tf32(a00));
        A0[0][1] = __float_as_uint(to_tf32(a01));
        A0[0][2] = __float_as_uint(to_tf32(a02));
        A0[0][3] = __float_as_uint(to_tf32(a03));
        A0[1][0] = __float_as_uint(to_tf32(a10));
        A0[1][1] = __float_as_uint(to_tf32(a11));
        A0[1][2] = __float_as_uint(to_tf32(a12));
        A0[1][3] = __float_as_uint(to_tf32(a13));

        // B fragments from smem (12 LDS.32)
        uint32_t bf[6][2];
        #pragma unroll
        for (int ni = 0; ni < 6; ni++) {
            int n = nw * 48 + ni * 8 + g;
            bf[ni][0] = __float_as_uint(Wt[n * WSTR + kb + tg]);
            bf[ni][1] = __float_as_uint(Wt[n * WSTR + kb + tg + 4]);
        }

        #pragma unroll
        for (int mi = 0; mi < 2; mi++)
            #pragma unroll
            for (int ni = 0; ni < 6; ni++)
                mma_tf32(acc[mi][ni], A0[mi][0], A0[mi][1], A0[mi][2], A0[mi][3],
                         bf[ni][0], bf[ni][1]);
    }

    // epilogue: per-thread cols = nw*48 + ni*8 + 2*tg (+1)
    float sc[6][2], sh[6][2];
    #pragma unroll
    for (int ni = 0; ni < 6; ni++)
        #pragma unroll
        for (int jj = 0; jj < 2; jj++) {
            int c = nw * 48 + ni * 8 + 2 * tg + jj;
            if (HAS_BN) {
                float s = gamma[c] * rsqrtf(rvar[c] + BN_EPS);
                sc[ni][jj] = s;
                sh[ni][jj] = (bias[c] - rmean[c]) * s + beta[c];
            } else {
                sc[ni][jj] = 1.f;
                sh[ni][jj] = bias[c];
            }
        }

    #pragma unroll
    for (int mi = 0; mi < 2; mi++) {
        int ra = rl + mi * 16;
        int rb = ra + 8;
        #pragma unroll
        for (int ni = 0; ni < 6; ni++) {
            int col = nw * 48 + ni * 8 + 2 * tg;
            if (ra < N_NODES) {
                float2 o;
                o.x = fmaxf(fmaf(acc[mi][ni][0], sc[ni][0], sh[ni][0]), 0.f);
                o.y = fmaxf(fmaf(acc[mi][ni][1], sc[ni][1], sh[ni][1]), 0.f);
                *(float2*)(out + (size_t)ra * H + col) = o;
                if (DUAL) *(float2*)(out2 + (size_t)ra * H + col) = o;
            }
            if (rb < N_NODES) {
                float2 o;
                o.x = fmaxf(fmaf(acc[mi][ni][2], sc[ni][0], sh[ni][0]), 0.f);
                o.y = fmaxf(fmaf(acc[mi][ni][3], sc[ni][1], sh[ni][1]), 0.f);
                *(float2*)(out + (size_t)rb * H + col) = o;
                if (DUAL) *(float2*)(out2 + (size_t)rb * H + col) = o;
            }
        }
    }
}

// ---------------- pooling (batch sorted -> segment sums, no atomics) ----------
__global__ void __launch_bounds__(96) pool_kernel(const int* __restrict__ batch,
                                                  float* __restrict__ pool) {
    int b = blockIdx.x;
    int c = threadIdx.x;
    int lo = 0, hi = N_NODES;
    while (lo < hi) { int m = (lo + hi) >> 1; if (batch[m] < b) lo = m + 1; else hi = m; }
    int start = lo;
    hi = N_NODES;
    while (lo < hi) { int m = (lo + hi) >> 1; if (batch[m] < b + 1) lo = m + 1; else hi = m; }
    int end = lo;

    float acc = 0.f;
    for (int n = start; n < end; n++)
        acc += g_h[(size_t)n * HID + c];
    pool[b * HID + c] = acc;
}

__global__ void head_kernel(const int* __restrict__ r_target,
                            const float* __restrict__ head_w,
                            const float* __restrict__ head_b,
                            const float* __restrict__ pool,
                            float* __restrict__ out) {
    int b = threadIdx.x;
    if (b >= N_GRAPHS) return;
    int t = r_target[b];
    const float4* w = (const float4*)(head_w + (size_t)t * HID);
    const float4* p = (const float4*)(pool + (size_t)b * HID);
    float acc = 0.f;
    #pragma unroll
    for (int k = 0; k < HID / 4; k++) {
        float4 wv = w[k], pv = p[k];
        acc = fmaf(pv.x, wv.x, acc);
        acc = fmaf(pv.y, wv.y, acc);
        acc = fmaf(pv.z, wv.z, acc);
        acc = fmaf(pv.w, wv.w, acc);
    }
    out[b] = acc + head_b[t];
}

// ---------------- launch ----------------
extern "C" void kernel_launch(void* const* d_in, const int* in_sizes, int n_in,
                              void* d_out, int out_size) {
    const float* x    = (const float*)d_in[0];
    const int*   ei   = (const int*)d_in[1];
    const int*   bat  = (const int*)d_in[2];
    const int*   rtg  = (const int*)d_in[3];

    const float* w_in[3]  = {(const float*)d_in[4],  (const float*)d_in[12], (const float*)d_in[20]};
    const float* b_in[3]  = {(const float*)d_in[5],  (const float*)d_in[13], (const float*)d_in[21]};
    const float* gam[3]   = {(const float*)d_in[6],  (const float*)d_in[14], (const float*)d_in[22]};
    const float* bet[3]   = {(const float*)d_in[7],  (const float*)d_in[15], (const float*)d_in[23]};
    const float* rme[3]   = {(const float*)d_in[8],  (const float*)d_in[16], (const float*)d_in[24]};
    const float* rva[3]   = {(const float*)d_in[9],  (const float*)d_in[17], (const float*)d_in[25]};
    const float* w_out[3] = {(const float*)d_in[10], (const float*)d_in[18], (const float*)d_in[26]};
    const float* b_out[3] = {(const float*)d_in[11], (const float*)d_in[19], (const float*)d_in[27]};
    const float* head_w   = (const float*)d_in[28];
    const float* head_b   = (const float*)d_in[29];
    float* out = (float*)d_out;

    float *hbuf, *aggbuf, *zbuf, *poolbuf;
    cudaGetSymbolAddress((void**)&hbuf, g_h);
    cudaGetSymbolAddress((void**)&aggbuf, g_agg);
    cudaGetSymbolAddress((void**)&zbuf, g_z);
    cudaGetSymbolAddress((void**)&poolbuf, g_pool);

    const int TB = 256;
    const int GB = 256;
    const int gemm_blocks = (N_NODES + 127) / 128;

    // ---- layer 1 (Din=32) ----
    copy_x_kernel<<<(N_NODES * DIN0 / 4 + TB - 1) / TB, TB>>>(x);
    {
        int tot = N_EDGES * (DIN0 / 4);
        edge_kernel<DIN0><<<(tot + TB - 1) / TB, TB>>>(x, ei, aggbuf);
    }
    gemm_kernel<DIN0, true, false><<<gemm_blocks, GB>>>(
        aggbuf, w_in[0], b_in[0], gam[0], bet[0], rme[0], rva[0], zbuf, nullptr);
    gemm_kernel<HID, false, true><<<gemm_blocks, GB>>>(
        zbuf, w_out[0], b_out[0], nullptr, nullptr, nullptr, nullptr, hbuf, aggbuf);

    // ---- layer 2 ----
    {
        int tot = N_EDGES * (HID / 4);
        edge_kernel<HID><<<(tot + TB - 1) / TB, TB>>>(hbuf, ei, aggbuf);
    }
    gemm_kernel<HID, true, false><<<gemm_blocks, GB>>>(
        aggbuf, w_in[1], b_in[1], gam[1], bet[1], rme[1], rva[1], zbuf, nullptr);
    gemm_kernel<HID, false, true><<<gemm_blocks, GB>>>(
        zbuf, w_out[1], b_out[1], nullptr, nullptr, nullptr, nullptr, hbuf, aggbuf);

    // ---- layer 3 ----
    {
        int tot = N_EDGES * (HID / 4);
        edge_kernel<HID><<<(tot + TB - 1) / TB, TB>>>(hbuf, ei, aggbuf);
    }
    gemm_kernel<HID, true, false><<<gemm_blocks, GB>>>(
        aggbuf, w_in[2], b_in[2], gam[2], bet[2], rme[2], rva[2], zbuf, nullptr);
    gemm_kernel<HID, false, false><<<gemm_blocks, GB>>>(
        zbuf, w_out[2], b_out[2], nullptr, nullptr, nullptr, nullptr, hbuf, nullptr);

    // ---- pooling + head ----
    pool_kernel<<<N_GRAPHS, 96>>>(bat, poolbuf);
    head_kernel<<<1, 256>>>(rtg, head_w, head_b, poolbuf, out);
}

// round 15
// speedup vs baseline: 1.3908x; 1.3364x over previous
#include <cuda_runtime.h>
#include <cuda_bf16.h>
#include <stdint.h>

#define N_NODES 50000
#define N_EDGES 800000
#define N_GRAPHS 256
#define DIN0 32
#define HID 96
#define BN_EPS 1e-5f

// ---------------- device scratch (static, allowed) ----------------
__device__ float g_h[(size_t)N_NODES * HID];
__device__ float g_agg[(size_t)N_NODES * HID];
__device__ float g_z[(size_t)N_NODES * HID];
__device__ float g_pool[N_GRAPHS * HID];
__device__ int   g_deg[N_NODES];
__device__ int   g_cur[N_NODES];
__device__ int   g_rowptr[N_NODES + 1];
__device__ int   g_col[N_EDGES];
__device__ int   g_bsum[256];

__device__ __forceinline__ float to_tf32(float x) {
    uint32_t u;
    asm("cvt.rna.tf32.f32 %0, %1;" : "=r"(u) : "f"(x));
    return __uint_as_float(u);
}

__device__ __forceinline__ void mma_tf32(float* c, uint32_t a0, uint32_t a1,
                                         uint32_t a2, uint32_t a3,
                                         uint32_t b0, uint32_t b1) {
    asm volatile(
        "mma.sync.aligned.m16n8k8.row.col.f32.tf32.tf32.f32 "
        "{%0,%1,%2,%3}, {%4,%5,%6,%7}, {%8,%9}, {%0,%1,%2,%3};"
        : "+f"(c[0]), "+f"(c[1]), "+f"(c[2]), "+f"(c[3])
        : "r"(a0), "r"(a1), "r"(a2), "r"(a3), "r"(b0), "r"(b1));
}

// ---------------- CSR build ----------------
__global__ void zero_deg_kernel() {
    int i = blockIdx.x * blockDim.x + threadIdx.x;
    if (i < N_NODES) g_deg[i] = 0;
}

// histogram of destinations, 4 edges per thread (int4 loads)
__global__ void hist_kernel(const int* __restrict__ ei) {
    int t = blockIdx.x * blockDim.x + threadIdx.x;
    if (t >= N_EDGES / 4) return;
    int4 d = *(const int4*)(ei + N_EDGES + 4 * t);
    atomicAdd(&g_deg[d.x], 1);
    atomicAdd(&g_deg[d.y], 1);
    atomicAdd(&g_deg[d.z], 1);
    atomicAdd(&g_deg[d.w], 1);
}

__device__ __forceinline__ int warp_red(int v) {
    #pragma unroll
    for (int o = 16; o > 0; o >>= 1) v += __shfl_down_sync(0xffffffffu, v, o);
    return v;
}

// per-block sums of deg chunks
__global__ void scan_partial_kernel() {
    __shared__ int ws[8];
    int tid = threadIdx.x;
    int i = blockIdx.x * 256 + tid;
    int v = (i < N_NODES) ? g_deg[i] : 0;
    int lane = tid & 31, w = tid >> 5;
    int s = warp_red(v);
    if (lane == 0) ws[w] = s;
    __syncthreads();
    if (tid == 0) {
        int tot = 0;
        #pragma unroll
        for (int k = 0; k < 8; k++) tot += ws[k];
        g_bsum[blockIdx.x] = tot;
    }
}

// exclusive scan of the (<=256) block sums, in place
__global__ void scan_bsums_kernel(int nb) {
    __shared__ int ws[8];
    int tid = threadIdx.x;
    int lane = tid & 31, w = tid >> 5;
    int v = (tid < nb) ? g_bsum[tid] : 0;
    int inc = v;
    #pragma unroll
    for (int o = 1; o < 32; o <<= 1) {
        int u = __shfl_up_sync(0xffffffffu, inc, o);
        if (lane >= o) inc += u;
    }
    if (lane == 31) ws[w] = inc;
    __syncthreads();
    if (w == 0) {
        int s = (lane < 8) ? ws[lane] : 0;
        #pragma unroll
        for (int o = 1; o < 8; o <<= 1) {
            int u = __shfl_up_sync(0xffffffffu, s, o);
            if (lane >= o) s += u;
        }
        if (lane < 8) ws[lane] = s;
    }
    __syncthreads();
    int woff = (w > 0) ? ws[w - 1] : 0;
    if (tid < nb) g_bsum[tid] = woff + inc - v;   // exclusive
}

// final: rowptr[i] = bsum[b] + in-block exclusive scan; also cursor copy
__global__ void scan_final_kernel() {
    __shared__ int ws[8];
    int tid = threadIdx.x;
    int i = blockIdx.x * 256 + tid;
    int v = (i < N_NODES) ? g_deg[i] : 0;
    int lane = tid & 31, w = tid >> 5;
    int inc = v;
    #pragma unroll
    for (int o = 1; o < 32; o <<= 1) {
        int u = __shfl_up_sync(0xffffffffu, inc, o);
        if (lane >= o) inc += u;
    }
    if (lane == 31) ws[w] = inc;
    __syncthreads();
    if (w == 0) {
        int s = (lane < 8) ? ws[lane] : 0;
        #pragma unroll
        for (int o = 1; o < 8; o <<= 1) {
            int u = __shfl_up_sync(0xffffffffu, s, o);
            if (lane >= o) s += u;
        }
        if (lane < 8) ws[lane] = s;
    }
    __syncthreads();
    int woff = (w > 0) ? ws[w - 1] : 0;
    int excl = g_bsum[blockIdx.x] + woff + inc - v;
    if (i < N_NODES) { g_rowptr[i] = excl; g_cur[i] = excl; }
    if (i == 0) g_rowptr[N_NODES] = N_EDGES;
}

// scatter sources into dst buckets, 4 edges per thread
__global__ void fill_kernel(const int* __restrict__ ei) {
    int t = blockIdx.x * blockDim.x + threadIdx.x;
    if (t >= N_EDGES / 4) return;
    int4 s = *(const int4*)(ei + 4 * t);
    int4 d = *(const int4*)(ei + N_EDGES + 4 * t);
    g_col[atomicAdd(&g_cur[d.x], 1)] = s.x;
    g_col[atomicAdd(&g_cur[d.y], 1)] = s.y;
    g_col[atomicAdd(&g_cur[d.z], 1)] = s.z;
    g_col[atomicAdd(&g_cur[d.w], 1)] = s.w;
}

// ---------------- gather aggregation: agg[n] = h[n] + sum_{j->n} h[j] --------
// thread = (node, float4-lane); DIN/4 threads per node; float4 everywhere.
template<int DIN>
__global__ void __launch_bounds__(256) gather_kernel(const float* __restrict__ h,
                                                     float* __restrict__ agg) {
    const int VPR = DIN / 4;
    int t = blockIdx.x * blockDim.x + threadIdx.x;
    int n = t / VPR;
    int lane = t - n * VPR;
    if (n >= N_NODES) return;
    int e   = g_rowptr[n];
    int end = g_rowptr[n + 1];

    float4 a = *(const float4*)(h + (size_t)n * DIN + lane * 4);  // self term

    #pragma unroll 1
    for (; e + 4 <= end; e += 4) {
        int s0 = g_col[e], s1 = g_col[e+1], s2 = g_col[e+2], s3 = g_col[e+3];
        float4 v0 = *(const float4*)(h + (size_t)s0 * DIN + lane * 4);
        float4 v1 = *(const float4*)(h + (size_t)s1 * DIN + lane * 4);
        float4 v2 = *(const float4*)(h + (size_t)s2 * DIN + lane * 4);
        float4 v3 = *(const float4*)(h + (size_t)s3 * DIN + lane * 4);
        a.x += v0.x + v1.x + v2.x + v3.x;
        a.y += v0.y + v1.y + v2.y + v3.y;
        a.z += v0.z + v1.z + v2.z + v3.z;
        a.w += v0.w + v1.w + v2.w + v3.w;
    }
    for (; e < end; e++) {
        float4 v = *(const float4*)(h + (size_t)g_col[e] * DIN + lane * 4);
        a.x += v.x; a.y += v.y; a.z += v.z; a.w += v.w;
    }
    *(float4*)(agg + (size_t)n * DIN + lane * 4) = a;
}

// ---------------- TF32 tensor-core GEMM (exact R10 best variant) -------------
template<int DIN, bool HAS_BN>
__global__ void __launch_bounds__(256, 3) gemm_kernel(
    const float* __restrict__ A, const float* __restrict__ W,
    const float* __restrict__ bias,
    const float* __restrict__ gamma, const float* __restrict__ beta,
    const float* __restrict__ rmean, const float* __restrict__ rvar,
    float* __restrict__ out)
{
    constexpr int H = 96;
    constexpr int NKC = DIN / 8;
    constexpr int WSTR = DIN + 4;
    __shared__ float Wt[H * WSTR];
    __shared__ float As[2][8][136];

    const int tid  = threadIdx.x;
    const int warp = tid >> 5;
    const int lane = tid & 31;
    const int g    = lane >> 2;
    const int tg   = lane & 3;
    const int mw   = warp & 3;
    const int nw   = warp >> 2;
    const int row0 = blockIdx.x * 128;

    for (int i = tid; i < DIN * H; i += 256) {
        int k = i / H, n = i - k * H;
        Wt[n * WSTR + k] = to_tf32(W[i]);
    }

    const int r  = tid & 127;
    const int kv = tid >> 7;

    float acc[2][6][4];
    #pragma unroll
    for (int mi = 0; mi < 2; mi++)
        #pragma unroll
        for (int ni = 0; ni < 6; ni++)
            #pragma unroll
            for (int q = 0; q < 4; q++) acc[mi][ni][q] = 0.f;

    {
        int gr = row0 + r;
        float4 v = (gr < N_NODES)
            ? *(const float4*)(A + (size_t)gr * DIN + kv * 4)
            : make_float4(0.f, 0.f, 0.f, 0.f);
        As[0][kv * 4 + 0][r] = to_tf32(v.x);
        As[0][kv * 4 + 1][r] = to_tf32(v.y);
        As[0][kv * 4 + 2][r] = to_tf32(v.z);
        As[0][kv * 4 + 3][r] = to_tf32(v.w);
    }
    __syncthreads();

    int buf = 0;
    for (int kt = 0; kt < NKC; kt++) {
        float4 nv;
        if (kt + 1 < NKC) {
            int gr = row0 + r;
            nv = (gr < N_NODES)
                ? *(const float4*)(A + (size_t)gr * DIN + (kt + 1) * 8 + kv * 4)
                : make_float4(0.f, 0.f, 0.f, 0.f);
        }

        const int kb = kt * 8;
        uint32_t bf[6][2];
        #pragma unroll
        for (int ni = 0; ni < 6; ni++) {
            int n = nw * 48 + ni * 8 + g;
            bf[ni][0] = __float_as_uint(Wt[n * WSTR + kb + tg]);
            bf[ni][1] = __float_as_uint(Wt[n * WSTR + kb + tg + 4]);
        }
        #pragma unroll
        for (int mi = 0; mi < 2; mi++) {
            int ra = mw * 32 + mi * 16 + g;
            uint32_t a0 = __float_as_uint(As[buf][tg][ra]);
            uint32_t a1 = __float_as_uint(As[buf][tg][ra + 8]);
            uint32_t a2 = __float_as_uint(As[buf][tg + 4][ra]);
            uint32_t a3 = __float_as_uint(As[buf][tg + 4][ra + 8]);
            #pragma unroll
            for (int ni = 0; ni < 6; ni++)
                mma_tf32(acc[mi][ni], a0, a1, a2, a3, bf[ni][0], bf[ni][1]);
        }

        if (kt + 1 < NKC) {
            As[buf ^ 1][kv * 4 + 0][r] = to_tf32(nv.x);
            As[buf ^ 1][kv * 4 + 1][r] = to_tf32(nv.y);
            As[buf ^ 1][kv * 4 + 2][r] = to_tf32(nv.z);
            As[buf ^ 1][kv * 4 + 3][r] = to_tf32(nv.w);
            __syncthreads();
        }
        buf ^= 1;
    }

    float sc[6][2], sh[6][2];
    #pragma unroll
    for (int ni = 0; ni < 6; ni++)
        #pragma unroll
        for (int jj = 0; jj < 2; jj++) {
            int c = nw * 48 + ni * 8 + 2 * tg + jj;
            if (HAS_BN) {
                float s = gamma[c] * rsqrtf(rvar[c] + BN_EPS);
                sc[ni][jj] = s;
                sh[ni][jj] = (bias[c] - rmean[c]) * s + beta[c];
            } else {
                sc[ni][jj] = 1.f;
                sh[ni][jj] = bias[c];
            }
        }

    #pragma unroll
    for (int mi = 0; mi < 2; mi++) {
        int ra = row0 + mw * 32 + mi * 16 + g;
        int rb = ra + 8;
        #pragma unroll
        for (int ni = 0; ni < 6; ni++) {
            int col = nw * 48 + ni * 8 + 2 * tg;
            if (ra < N_NODES) {
                float2 o;
                o.x = fmaxf(fmaf(acc[mi][ni][0], sc[ni][0], sh[ni][0]), 0.f);
                o.y = fmaxf(fmaf(acc[mi][ni][1], sc[ni][1], sh[ni][1]), 0.f);
                *(float2*)(out + (size_t)ra * H + col) = o;
            }
            if (rb < N_NODES) {
                float2 o;
                o.x = fmaxf(fmaf(acc[mi][ni][2], sc[ni][0], sh[ni][0]), 0.f);
                o.y = fmaxf(fmaf(acc[mi][ni][3], sc[ni][1], sh[ni][1]), 0.f);
                *(float2*)(out + (size_t)rb * H + col) = o;
            }
        }
    }
}

// ---------------- pooling (batch sorted -> segment sums, no atomics) ----------
__global__ void __launch_bounds__(96) pool_kernel(const int* __restrict__ batch,
                                                  float* __restrict__ pool) {
    int b = blockIdx.x;
    int c = threadIdx.x;
    int lo = 0, hi = N_NODES;
    while (lo < hi) { int m = (lo + hi) >> 1; if (batch[m] < b) lo = m + 1; else hi = m; }
    int start = lo;
    hi = N_NODES;
    while (lo < hi) { int m = (lo + hi) >> 1; if (batch[m] < b + 1) lo = m + 1; else hi = m; }
    int end = lo;

    float acc = 0.f;
    for (int n = start; n < end; n++)
        acc += g_h[(size_t)n * HID + c];
    pool[b * HID + c] = acc;
}

__global__ void head_kernel(const int* __restrict__ r_target,
                            const float* __restrict__ head_w,
                            const float* __restrict__ head_b,
                            const float* __restrict__ pool,
                            float* __restrict__ out) {
    int b = threadIdx.x;
    if (b >= N_GRAPHS) return;
    int t = r_target[b];
    const float4* w = (const float4*)(head_w + (size_t)t * HID);
    const float4* p = (const float4*)(pool + (size_t)b * HID);
    float acc = 0.f;
    #pragma unroll
    for (int k = 0; k < HID / 4; k++) {
        float4 wv = w[k], pv = p[k];
        acc = fmaf(pv.x, wv.x, acc);
        acc = fmaf(pv.y, wv.y, acc);
        acc = fmaf(pv.z, wv.z, acc);
        acc = fmaf(pv.w, wv.w, acc);
    }
    out[b] = acc + head_b[t];
}

// ---------------- launch ----------------
extern "C" void kernel_launch(void* const* d_in, const int* in_sizes, int n_in,
                              void* d_out, int out_size) {
    const float* x    = (const float*)d_in[0];
    const int*   ei   = (const int*)d_in[1];
    const int*   bat  = (const int*)d_in[2];
    const int*   rtg  = (const int*)d_in[3];

    const float* w_in[3]  = {(const float*)d_in[4],  (const float*)d_in[12], (const float*)d_in[20]};
    const float* b_in[3]  = {(const float*)d_in[5],  (const float*)d_in[13], (const float*)d_in[21]};
    const float* gam[3]   = {(const float*)d_in[6],  (const float*)d_in[14], (const float*)d_in[22]};
    const float* bet[3]   = {(const float*)d_in[7],  (const float*)d_in[15], (const float*)d_in[23]};
    const float* rme[3]   = {(const float*)d_in[8],  (const float*)d_in[16], (const float*)d_in[24]};
    const float* rva[3]   = {(const float*)d_in[9],  (const float*)d_in[17], (const float*)d_in[25]};
    const float* w_out[3] = {(const float*)d_in[10], (const float*)d_in[18], (const float*)d_in[26]};
    const float* b_out[3] = {(const float*)d_in[11], (const float*)d_in[19], (const float*)d_in[27]};
    const float* head_w   = (const float*)d_in[28];
    const float* head_b   = (const float*)d_in[29];
    float* out = (float*)d_out;

    float *hbuf, *aggbuf, *zbuf, *poolbuf;
    cudaGetSymbolAddress((void**)&hbuf, g_h);
    cudaGetSymbolAddress((void**)&aggbuf, g_agg);
    cudaGetSymbolAddress((void**)&zbuf, g_z);
    cudaGetSymbolAddress((void**)&poolbuf, g_pool);

    const int TB = 256;
    const int GB = 256;
    const int gemm_blocks = (N_NODES + 127) / 128;
    const int nb_scan = (N_NODES + 255) / 256;           // 196
    const int eb4 = (N_EDGES / 4 + TB - 1) / TB;         // 782

    // ---- CSR build (dst-bucketed) ----
    zero_deg_kernel<<<nb_scan, TB>>>();
    hist_kernel<<<eb4, TB>>>(ei);
    scan_partial_kernel<<<nb_scan, TB>>>();
    scan_bsums_kernel<<<1, 256>>>(nb_scan);
    scan_final_kernel<<<nb_scan, TB>>>();
    fill_kernel<<<eb4, TB>>>(ei);

    // ---- layer 1 (Din=32) ----
    gather_kernel<DIN0><<<(N_NODES * (DIN0/4) + TB - 1) / TB, TB>>>(x, aggbuf);
    gemm_kernel<DIN0, true><<<gemm_blocks, GB>>>(
        aggbuf, w_in[0], b_in[0], gam[0], bet[0], rme[0], rva[0], zbuf);
    gemm_kernel<HID, false><<<gemm_blocks, GB>>>(
        zbuf, w_out[0], b_out[0], nullptr, nullptr, nullptr, nullptr, hbuf);

    // ---- layer 2 ----
    gather_kernel<HID><<<(N_NODES * (HID/4) + TB - 1) / TB, TB>>>(hbuf, aggbuf);
    gemm_kernel<HID, true><<<gemm_blocks, GB>>>(
        aggbuf, w_in[1], b_in[1], gam[1], bet[1], rme[1], rva[1], zbuf);
    gemm_kernel<HID, false><<<gemm_blocks, GB>>>(
        zbuf, w_out[1], b_out[1], nullptr, nullptr, nullptr, nullptr, hbuf);

    // ---- layer 3 ----
    gather_kernel<HID><<<(N_NODES * (HID/4) + TB - 1) / TB, TB>>>(hbuf, aggbuf);
    gemm_kernel<HID, true><<<gemm_blocks, GB>>>(
        aggbuf, w_in[2], b_in[2], gam[2], bet[2], rme[2], rva[2], zbuf);
    gemm_kernel<HID, false><<<gemm_blocks, GB>>>(
        zbuf, w_out[2], b_out[2], nullptr, nullptr, nullptr, nullptr, hbuf);

    // ---- pooling + head ----
    pool_kernel<<<N_GRAPHS, 96>>>(bat, poolbuf);
    head_kernel<<<1, 256>>>(rtg, head_w, head_b, poolbuf, out);
}